// round 6
// baseline (speedup 1.0000x reference)
#include <cuda_runtime.h>
#include <cuda_fp16.h>
#include <cstdint>
#include <math.h>

// Problem dims
#define BNROWS 32768   // B*N
#define DDIM   256
#define KCODES 1024

// Output layout (float32, reference return order)
#define OFF_Q      0ull
#define OFF_DICT   8388608ull
#define OFF_COMMIT 8388609ull
#define OFF_IDX    8388610ull
#define OFF_PERP   8421378ull

// ---------------- scratch (device globals) -----------------------------------
__device__ float  g_partS [256][DDIM];
__device__ float  g_partS2[256][DDIM];
__device__ float  g_partC [256];
__device__ float  g_cnt;
__device__ __align__(16) float g_scale[DDIM];
__device__ __align__(16) float g_shift[DDIM];
__device__ __align__(16) __half g_eB2[(size_t)KCODES * 512]; // [e_h(256) | e_l(256)]
__device__ __align__(16) float g_ET[(size_t)KCODES * DDIM];  // codebook^T [K][D]
__device__ __align__(16) float g_csq[KCODES];
__device__ float  g_xsq[BNROWS];
__device__ unsigned long long g_packed[BNROWS];   // (monotone(dist)<<32)|idx
__device__ float  g_counts[KCODES];
__device__ double g_loss;
__device__ int    g_ticket;

// ---------------- helpers ------------------------------------------------------
__device__ __forceinline__ uint32_t s2u(const void* p) {
    uint32_t a;
    asm("{ .reg .u64 t; cvta.to.shared.u64 t, %1; cvt.u32.u64 %0, t; }" : "=r"(a) : "l"(p));
    return a;
}
__device__ __forceinline__ uint32_t swz(uint32_t off) { return off ^ ((off >> 3) & 0x70); }

__device__ __forceinline__ void cp16(uint32_t dst, const void* src) {
    asm volatile("cp.async.cg.shared.global [%0], [%1], 16;" :: "r"(dst), "l"(src) : "memory");
}
#define CP_COMMIT() asm volatile("cp.async.commit_group;" ::: "memory")
#define CP_WAIT(N)  asm volatile("cp.async.wait_group %0;" :: "n"(N) : "memory")

__device__ __forceinline__ void ldsm_x4(uint32_t* r, uint32_t addr) {
    asm volatile("ldmatrix.sync.aligned.m8n8.x4.shared.b16 {%0,%1,%2,%3}, [%4];"
                 : "=r"(r[0]), "=r"(r[1]), "=r"(r[2]), "=r"(r[3]) : "r"(addr));
}
__device__ __forceinline__ void mma16816(float* c, const uint32_t* a, const uint32_t* b) {
    asm volatile(
        "mma.sync.aligned.m16n8k16.row.col.f32.f16.f16.f32 "
        "{%0,%1,%2,%3}, {%4,%5,%6,%7}, {%8,%9}, {%0,%1,%2,%3};"
        : "+f"(c[0]), "+f"(c[1]), "+f"(c[2]), "+f"(c[3])
        : "r"(a[0]), "r"(a[1]), "r"(a[2]), "r"(a[3]), "r"(b[0]), "r"(b[1]));
}

// ---------------- K1: masked stats partials + init packed/csq -------------------
__global__ void k_stats(const float* __restrict__ x, const int* __restrict__ mask) {
    int d4 = threadIdx.x;   // 0..63 (float4 columns)
    int ty = threadIdx.y;   // 0..3
    int b  = blockIdx.x;
    int gid = b * 256 + ty * 64 + d4;
    if (gid < BNROWS) g_packed[gid] = 0xFFFFFFFFFFFFFFFFull;
    if (gid < KCODES) g_csq[gid] = 0.f;

    int r0 = b * 128 + ty * 32;
    const float4* x4 = (const float4*)x;
    float4 s  = make_float4(0.f, 0.f, 0.f, 0.f);
    float4 s2 = make_float4(0.f, 0.f, 0.f, 0.f);
    float  c  = 0.f;
    for (int r = 0; r < 32; r++) {
        if (mask[r0 + r]) {
            float4 v = x4[(size_t)(r0 + r) * 64 + d4];
            s.x += v.x; s.y += v.y; s.z += v.z; s.w += v.w;
            s2.x += v.x * v.x; s2.y += v.y * v.y; s2.z += v.z * v.z; s2.w += v.w * v.w;
            c += 1.f;
        }
    }
    __shared__ float4 sS[4][64], sS2[4][64];
    __shared__ float  sC[4];
    sS[ty][d4] = s; sS2[ty][d4] = s2;
    if (d4 == 0) sC[ty] = c;
    __syncthreads();
    if (ty == 0) {
        for (int y = 1; y < 4; y++) {
            float4 a = sS[y][d4], a2 = sS2[y][d4];
            s.x += a.x; s.y += a.y; s.z += a.z; s.w += a.w;
            s2.x += a2.x; s2.y += a2.y; s2.z += a2.z; s2.w += a2.w;
        }
        ((float4*)g_partS [b])[d4] = s;
        ((float4*)g_partS2[b])[d4] = s2;
        if (d4 == 0) g_partC[b] = sC[0] + sC[1] + sC[2] + sC[3];
    }
}

// ---------------- K2: transpose E + fp16 split + csq partials --------------------
__global__ void k_prep_e(const float* __restrict__ E) {
    __shared__ float t[32][33];
    int tx = threadIdx.x, ty = threadIdx.y;
    int x0 = blockIdx.x * 32;  // code
    int y0 = blockIdx.y * 32;  // d
    for (int j = ty; j < 32; j += 8)
        t[j][tx] = E[(size_t)(y0 + j) * KCODES + x0 + tx];
    __syncthreads();
    for (int j = ty; j < 32; j += 8) {
        int code = x0 + j, d = y0 + tx;
        float v = t[tx][j];
        g_ET[(size_t)code * DDIM + d] = v;
        __half h = __float2half_rn(v);
        g_eB2[(size_t)code * 512 + d]       = h;
        g_eB2[(size_t)code * 512 + 256 + d] = __float2half_rn(v - __half2float(h));
        float sq = v * v;
        for (int o = 16; o; o >>= 1) sq += __shfl_down_sync(0xffffffffu, sq, o);
        if (tx == 0) atomicAdd(&g_csq[code], sq);
    }
}

// ---------------- K3: reduce stats -> scale/shift; zero counts/loss/ticket -------
__global__ void k_reduce_stats(const float* __restrict__ gamma, const float* __restrict__ beta) {
    int d = threadIdx.x;
    float s = 0.f, s2 = 0.f, cnt = 0.f;
#pragma unroll 8
    for (int b = 0; b < 256; b++) {
        s  += g_partS [b][d];
        s2 += g_partS2[b][d];
        cnt += g_partC[b];
    }
    for (int i = d; i < KCODES; i += 256) g_counts[i] = 0.f;
    if (d == 0) { g_cnt = cnt; g_loss = 0.0; g_ticket = 0; }
    float nv = fmaxf(cnt, 1.f);
    float mu  = s / nv;
    float var = s2 / nv - mu * mu;
    float sc  = rsqrtf(var + 1e-5f) * gamma[d];
    g_scale[d] = sc;
    g_shift[d] = beta[d] - mu * sc;
}

// ---------------- K4: persistent HMMA GEMM + argmin -------------------------------
// 2048 tiles = 256 row-tiles (128 rows) x 8 code-tiles (128 codes), atomic ticket,
// code-major so consecutive tickets reuse resident A. 512 threads = 16 warps
// (4m x 4n, warp tile 32x32). A built in-kernel from x. B: 8 chunks/tile, 5-stage.
#define NTILES  2048
#define B_OFF   131072
#define NSTG    5
#define CSQ_OFF (B_OFF + NSTG * 16384)    // 212992
#define XSQ_OFF (CSQ_OFF + 4096)          // 217088
#define RV_OFF  (XSQ_OFF + 1024)          // 218112
#define RI_OFF  (RV_OFF + 2048)           // 220160
#define TK_OFF  (RI_OFF + 2048)           // 222208
#define SMEMSZ  (TK_OFF + 16)             // 222224

__global__ void __launch_bounds__(512, 1) k_mma_argmin(const float* __restrict__ x) {
    extern __shared__ char smem[];
    const uint32_t sbA = s2u(smem);
    const uint32_t sbB = sbA + B_OFF;
    const int tid  = threadIdx.x;
    const int lane = tid & 31;
    const int wid  = tid >> 5;
    const int wm   = wid >> 2;       // 0..3
    const int wn   = wid & 3;        // 0..3

    if (tid < 256)
        ((float4*)(smem + CSQ_OFF))[tid] = ((const float4*)g_csq)[tid];
    int*   s_tk  = (int*)(smem + TK_OFF);
    float* sxsq  = (float*)(smem + XSQ_OFF);
    float* rv    = (float*)(smem + RV_OFF);   // [128][4]
    int*   ri    = (int*)(smem + RI_OFF);     // [128][4]
    const float* scsq = (const float*)(smem + CSQ_OFF);

    // per-thread fixed A column (for conversion)
    const int colA = tid & 63;
    const float4 scv = ((const float4*)g_scale)[colA];
    const float4 shv = ((const float4*)g_shift)[colA];

    const uint32_t aRow = (uint32_t)(wm * 32 + (lane & 15));
    const uint32_t aKG  = (uint32_t)((lane >> 4) << 4);
    // B x4: lanes 0-15 -> frag np*2 (rows lane&7, kg (lane>>3)&1), lanes 16-31 -> frag np*2+1
    const uint32_t bRow = (uint32_t)(wn * 32 + ((lane >> 4) << 3) + (lane & 7));
    const uint32_t bKG  = (uint32_t)(((lane >> 3) & 1) << 4);

    int cachedRow = -1;
    for (;;) {
        __syncthreads();
        if (tid == 0) *s_tk = atomicAdd(&g_ticket, 1);
        __syncthreads();
        const int tk = *s_tk;
        if (tk >= NTILES) break;
        const int rowTile  = tk >> 3;
        const int codeTile = tk & 7;
        const int rowBase  = rowTile << 7;
        const int codeBase = codeTile << 7;

        // ---- B prologue: chunks 0..3 into stages 0..3 ----
        {
            const char* bs = (const char*)(g_eB2 + (size_t)codeBase * 512);
#pragma unroll
            for (int c0 = 0; c0 < 4; c0++) {
#pragma unroll
                for (int v = 0; v < 2; v++) {
                    int idx = tid + v * 512;
                    int r = idx >> 3, j = idx & 7;
                    cp16(sbB + c0 * 16384 + swz((r << 7) + (j << 4)),
                         bs + ((size_t)r * 512 + c0 * 64 + j * 8) * 2);
                }
                CP_COMMIT();
            }
        }

        // ---- A load/convert (only when row-tile changes) ----
        if (rowTile != cachedRow) {
            cachedRow = rowTile;
            const float4* xs = (const float4*)(x + (size_t)rowBase * DDIM);
            const int kk = colA >> 4, jj = colA & 15;
            const uint32_t offh = sbA + kk * 16384;
#pragma unroll 4
            for (int i = 0; i < 16; i++) {
                int r = (tid >> 6) + i * 8;
                float4 v = xs[(size_t)r * 64 + colA];
                float b0 = v.x * scv.x + shv.x;
                float b1 = v.y * scv.y + shv.y;
                float b2 = v.z * scv.z + shv.z;
                float b3 = v.w * scv.w + shv.w;
                __half2 h01 = __floats2half2_rn(b0, b1);
                __half2 h23 = __floats2half2_rn(b2, b3);
                __half2 l01 = __floats2half2_rn(b0 - __low2float(h01), b1 - __high2float(h01));
                __half2 l23 = __floats2half2_rn(b2 - __low2float(h23), b3 - __high2float(h23));
                uint32_t so = swz((uint32_t)(r << 7) + (jj << 3));
                asm volatile("st.shared.v2.u32 [%0], {%1,%2};"
                             :: "r"(offh + so), "r"(*(uint32_t*)&h01), "r"(*(uint32_t*)&h23));
                asm volatile("st.shared.v2.u32 [%0], {%1,%2};"
                             :: "r"(offh + 65536 + so), "r"(*(uint32_t*)&l01), "r"(*(uint32_t*)&l23));
                float s = b0 * b0 + b1 * b1 + b2 * b2 + b3 * b3;
                for (int o = 16; o; o >>= 1) s += __shfl_down_sync(0xffffffffu, s, o);
                if (lane == 0) sxsq[r * 2 + (wid & 1)] = s;
            }
            __syncthreads();
            if (tid < 128) g_xsq[rowBase + tid] = sxsq[tid * 2] + sxsq[tid * 2 + 1];
        }

        // ---- mainloop: 8 chunks (eh 0-3, el 0-3) ----
        float acc[2][4][4];
        float best[4];
        int   bidx[4];
#pragma unroll
        for (int s = 0; s < 4; s++) { best[s] = 3.4e38f; bidx[s] = 0; }
#pragma unroll
        for (int mf = 0; mf < 2; mf++)
#pragma unroll
            for (int nf = 0; nf < 4; nf++)
#pragma unroll
                for (int t = 0; t < 4; t++) acc[mf][nf][t] = 0.f;

#pragma unroll 1
        for (int c = 0; c < 8; c++) {
            const int kk2 = c & 3;
            const bool dual = (c < 4);
            const int stage = (c >= NSTG) ? c - NSTG : c;

            if (c <= 4)      CP_WAIT(3);
            else if (c == 5) CP_WAIT(2);
            else if (c == 6) CP_WAIT(1);
            else             CP_WAIT(0);
            __syncthreads();

            const uint32_t bbase = sbB + stage * 16384;
            const uint32_t ah = sbA + kk2 * 16384;
            const uint32_t al = ah + 65536;
#pragma unroll
            for (int ks = 0; ks < 4; ks++) {
                uint32_t b[4][2];
#pragma unroll
                for (int np = 0; np < 2; np++) {
                    uint32_t bb[4];
                    ldsm_x4(bb, bbase + swz(((bRow + np * 16) << 7) + ks * 32 + bKG));
                    b[np * 2][0] = bb[0]; b[np * 2][1] = bb[1];
                    b[np * 2 + 1][0] = bb[2]; b[np * 2 + 1][1] = bb[3];
                }
                uint32_t a[2][4];
#pragma unroll
                for (int mf = 0; mf < 2; mf++)
                    ldsm_x4(a[mf], ah + swz(((aRow + mf * 16) << 7) + ks * 32 + aKG));
#pragma unroll
                for (int mf = 0; mf < 2; mf++)
#pragma unroll
                    for (int nf = 0; nf < 4; nf++)
                        mma16816(acc[mf][nf], a[mf], b[nf]);
                if (dual) {
                    uint32_t a2[2][4];
#pragma unroll
                    for (int mf = 0; mf < 2; mf++)
                        ldsm_x4(a2[mf], al + swz(((aRow + mf * 16) << 7) + ks * 32 + aKG));
#pragma unroll
                    for (int mf = 0; mf < 2; mf++)
#pragma unroll
                        for (int nf = 0; nf < 4; nf++)
                            mma16816(acc[mf][nf], a2[mf], b[nf]);
                }
            }

            if (c + 4 < 8) {
                const int cc = c + 4;
                const int st2 = (stage + 4 >= NSTG) ? stage + 4 - NSTG : stage + 4;
                const char* bs = (const char*)(g_eB2 + (size_t)codeBase * 512);
#pragma unroll
                for (int v = 0; v < 2; v++) {
                    int idx = tid + v * 512;
                    int r = idx >> 3, j = idx & 7;
                    cp16(sbB + st2 * 16384 + swz((r << 7) + (j << 4)),
                         bs + ((size_t)r * 512 + cc * 64 + j * 8) * 2);
                }
                CP_COMMIT();
            }
        }

        // ---- epilogue: distances + per-thread argmin ----
        {
            const float* csqp = scsq + codeBase + wn * 32 + 2 * (lane & 3);
#pragma unroll
            for (int nf = 0; nf < 4; nf++) {
                float q0 = csqp[nf * 8];
                float q1 = csqp[nf * 8 + 1];
                int n0 = codeBase + wn * 32 + nf * 8 + 2 * (lane & 3);
#pragma unroll
                for (int mf = 0; mf < 2; mf++) {
                    float d0 = q0 - 2.f * acc[mf][nf][0];
                    float d1 = q1 - 2.f * acc[mf][nf][1];
                    float d2 = q0 - 2.f * acc[mf][nf][2];
                    float d3 = q1 - 2.f * acc[mf][nf][3];
                    int s0 = mf * 2, s1 = mf * 2 + 1;
                    if (d0 < best[s0]) { best[s0] = d0; bidx[s0] = n0; }
                    if (d1 < best[s0]) { best[s0] = d1; bidx[s0] = n0 + 1; }
                    if (d2 < best[s1]) { best[s1] = d2; bidx[s1] = n0; }
                    if (d3 < best[s1]) { best[s1] = d3; bidx[s1] = n0 + 1; }
                }
            }
        }

        // ---- per-tile argmin reduce + global merge ----
        __syncthreads();
#pragma unroll
        for (int s = 0; s < 4; s++) {
            float v = best[s];
            int   ix = bidx[s];
#pragma unroll
            for (int off = 1; off <= 2; off <<= 1) {
                float ov = __shfl_xor_sync(0xffffffffu, v, off);
                int   oi = __shfl_xor_sync(0xffffffffu, ix, off);
                if (ov < v || (ov == v && oi < ix)) { v = ov; ix = oi; }
            }
            if ((lane & 3) == 0) {
                int row = wm * 32 + (s >> 1) * 16 + (lane >> 2) + (s & 1) * 8;
                rv[row * 4 + wn] = v;
                ri[row * 4 + wn] = ix;
            }
        }
        __syncthreads();
        if (tid < 128) {
            float bv = rv[tid * 4];
            int   bi = ri[tid * 4];
#pragma unroll
            for (int t = 1; t < 4; t++) {
                float v = rv[tid * 4 + t];
                int   i = ri[tid * 4 + t];
                if (v < bv || (v == bv && i < bi)) { bv = v; bi = i; }
            }
            unsigned ub = __float_as_uint(bv);
            unsigned key = ((int)ub < 0) ? ~ub : (ub | 0x80000000u);
            unsigned long long pk = ((unsigned long long)key << 32) | (unsigned)bi;
            atomicMin(&g_packed[rowBase + tid], pk);
        }
    }
}

// ---------------- K5: gather q, output, loss, counts, idx --------------------------
__global__ void k_quant(const int* __restrict__ mask,
                        float* __restrict__ outQ, float* __restrict__ outIdx) {
    int w = threadIdx.x >> 5, lane = threadIdx.x & 31;
    int row = blockIdx.x * 8 + w;
    int m = mask[row];
    unsigned long long pk = g_packed[row];
    int idx = (int)(pk & 0xffffffffull);
    const float4* qv = (const float4*)&g_ET[(size_t)idx * DDIM];
    float4* ov = (float4*)&outQ[(size_t)row * DDIM];
    float4 z = make_float4(0.f, 0.f, 0.f, 0.f);
#pragma unroll
    for (int t = 0; t < 2; t++) {
        int j = lane + t * 32;
        ov[j] = m ? qv[j] : z;
    }
    __shared__ float red[8];
    if (lane == 0) {
        unsigned key = (unsigned)(pk >> 32);
        unsigned ub = (key & 0x80000000u) ? (key & 0x7fffffffu) : ~key;
        float best = __uint_as_float(ub);
        red[w] = m ? (g_xsq[row] + best) : 0.f;
        outIdx[row] = m ? (float)idx : -1.f;
        if (m) atomicAdd(&g_counts[idx], 1.f);
    }
    __syncthreads();
    if (threadIdx.x == 0) {
        float t = 0.f;
        for (int i = 0; i < 8; i++) t += red[i];
        atomicAdd(&g_loss, (double)t);
    }
}

// ---------------- K6: finalize scalars -----------------------------------------------
__global__ void k_final(float* __restrict__ out) {
    int t = threadIdx.x;  // 1024 threads
    float nv = fmaxf(g_cnt, 1.f);
    float p = g_counts[t] / nv;
    float h = -p * logf(p + 1e-10f);
    for (int o = 16; o; o >>= 1) h += __shfl_down_sync(0xffffffffu, h, o);
    __shared__ float red[32];
    if ((t & 31) == 0) red[t >> 5] = h;
    __syncthreads();
    if (t < 32) {
        float s = red[t];
        for (int o = 16; o; o >>= 1) s += __shfl_down_sync(0xffffffffu, s, o);
        if (t == 0) {
            float loss = (float)(g_loss / ((double)nv * (double)DDIM));
            out[OFF_DICT]   = loss;
            out[OFF_COMMIT] = loss;
            out[OFF_PERP]   = expf(s);
        }
    }
}

// ---------------- launch ----------------------------------------------------------------
extern "C" void kernel_launch(void* const* d_in, const int* in_sizes, int n_in,
                              void* d_out, int out_size) {
    const float* x     = (const float*)d_in[0];
    const int*   mask  = (const int*)  d_in[1];
    const float* E     = (const float*)d_in[2];
    const float* gamma = (const float*)d_in[3];
    const float* beta  = (const float*)d_in[4];
    float* out = (float*)d_out;

    cudaFuncSetAttribute(k_mma_argmin, cudaFuncAttributeMaxDynamicSharedMemorySize, SMEMSZ);

    k_stats<<<256, dim3(64, 4)>>>(x, mask);                  // 1
    k_prep_e<<<dim3(32, 8), dim3(32, 8)>>>(E);               // 2
    k_reduce_stats<<<1, 256>>>(gamma, beta);                 // 3
    k_mma_argmin<<<148, 512, SMEMSZ>>>(x);                   // 4  (ncu lands here)
    k_quant<<<BNROWS / 8, 256>>>(mask, out + OFF_Q, out + OFF_IDX);
    k_final<<<1, 1024>>>(out);
}